// round 6
// baseline (speedup 1.0000x reference)
#include <cuda_runtime.h>
#include <math.h>
#include <stdint.h>

constexpr int H    = 128;
constexpr int G4   = 512;
constexpr int B    = 512;
constexpr int T    = 128;
constexpr int S    = 1536;   // 3 inputs * B
constexpr int NB   = 12;     // seqs per block
constexpr int NBLK = 128;
constexpr int NTH  = 512;

// k4-major packed weights: g_W[k4*512 + j] = {W[j][4k4..4k4+3]}
__device__ float4 g_W1h[32 * 512];
__device__ float4 g_W2i[32 * 512];
__device__ float4 g_W2h[32 * 512];
__device__ float  g_b1[512];
__device__ float  g_b2[512];
__device__ float  g_wx1[5 * 512];          // [d][j]
__device__ float  g_out1[(size_t)S * T * H];
__device__ float  g_lasth[S * H];
__device__ float  g_ps1[S * H];
__device__ float  g_pq1[S * H];
__device__ float  g_ps2[S * H];
__device__ float  g_pq2[S * H];
__device__ float2 g_bn1[3 * H];
__device__ float2 g_bn2[3 * H];

typedef unsigned long long ull;

__device__ __forceinline__ ull pk2(float x, float y) {
    ull r;
    asm("mov.b64 %0, {%1,%2};" : "=l"(r) : "r"(__float_as_uint(x)), "r"(__float_as_uint(y)));
    return r;
}
__device__ __forceinline__ float2 upk2(ull v) {
    unsigned lo, hi;
    asm("mov.b64 {%0,%1}, %2;" : "=r"(lo), "=r"(hi) : "l"(v));
    return make_float2(__uint_as_float(lo), __uint_as_float(hi));
}
__device__ __forceinline__ ull ffma2(ull a, ull b, ull c) {
    ull d;
    asm("fma.rn.f32x2 %0, %1, %2, %3;" : "=l"(d) : "l"(a), "l"(b), "l"(c));
    return d;
}
__device__ __forceinline__ float sigm(float x) {
    return __fdividef(1.f, 1.f + __expf(-x));
}
__device__ __forceinline__ float tanh_f(float x) {
    float e = __expf(-2.f * fabsf(x));
    float t = __fdividef(1.f - e, 1.f + e);
    return copysignf(t, x);
}

// ---------- pack weights ----------
__global__ void prep_kernel(const float* Wih1, const float* Whh1, const float* bih1, const float* bhh1,
                            const float* Wih2, const float* Whh2, const float* bih2, const float* bhh2) {
    int tid = blockIdx.x * blockDim.x + threadIdx.x;
    int stride = gridDim.x * blockDim.x;
    for (int idx = tid; idx < 32 * 512; idx += stride) {
        int k4 = idx >> 9, j = idx & 511;
        g_W1h[idx] = *(const float4*)&Whh1[j * H + 4 * k4];
        g_W2i[idx] = *(const float4*)&Wih2[j * H + 4 * k4];
        g_W2h[idx] = *(const float4*)&Whh2[j * H + 4 * k4];
    }
    for (int j = tid; j < 512; j += stride) {
        g_b1[j] = bih1[j] + bhh1[j];
        g_b2[j] = bih2[j] + bhh2[j];
        for (int d = 0; d < 5; d++) g_wx1[d * 512 + j] = Wih1[j * 5 + d];
    }
}

// ---------- layer 1 LSTM : 128 blocks x 512 thr, 12 seqs/block, 1 gate/thread ----------
__global__ void __launch_bounds__(NTH, 1)
lstm1_kernel(const float* __restrict__ xa, const float* __restrict__ xp, const float* __restrict__ xn) {
    __shared__ __align__(16) float hp[NB][H];    // 6 KB
    __shared__ float act[NB][G4];                // 24 KB
    __shared__ float xps[NB][5];

    const int tid = threadIdx.x;
    const int j = tid;
    const int sbase = blockIdx.x * NB;

    const float bias = g_b1[j];
    float wx[5];
#pragma unroll
    for (int d = 0; d < 5; d++) wx[d] = g_wx1[d * 512 + j];

    // phase-2 mapping: slot r -> u = tid + 512r, s = u>>7, m = u&127
    const int m  = tid & 127;
    const int sb = tid >> 7;                     // 0..3
    float csr[3] = {0,0,0}, sum[3] = {0,0,0}, sq[3] = {0,0,0};

    const float* xptr = xa; int xoff = 0, xsl = 0, xd = 0;
    if (tid < NB * 5) {
        xsl = tid / 5; xd = tid - 5 * xsl;
        int s = sbase + xsl, in = s >> 9, b = s & 511;
        xptr = (in == 0) ? xa : ((in == 1) ? xp : xn);
        xoff = b * (T * 5) + xd;
    }
    {
        float* f = &hp[0][0];
#pragma unroll
        for (int r = 0; r < 3; r++) f[tid + NTH * r] = 0.f;
    }
    __syncthreads();

    const int gt = j >> 7;  // 0:i 1:f 2:g 3:o

    for (int t = 0; t < T; t++) {
        if (tid < NB * 5) xps[xsl][xd] = __ldg(&xptr[xoff + t * 5]);
        __syncthreads();

        ull acc[NB];
#pragma unroll
        for (int s = 0; s < NB; s++) {
            float d0 = bias;
#pragma unroll
            for (int d = 0; d < 5; d++) d0 = fmaf(wx[d], xps[s][d], d0);
            acc[s] = pk2(d0, 0.f);
        }
        // double-buffered weight stream
        float4 wc = __ldg(&g_W1h[j]);
#pragma unroll 4
        for (int k4 = 0; k4 < 32; k4++) {
            float4 wn = __ldg(&g_W1h[(((k4 + 1) & 31) << 9) + j]);
            ull wlo = pk2(wc.x, wc.y), whi = pk2(wc.z, wc.w);
#pragma unroll
            for (int s = 0; s < NB; s++) {
                ulonglong2 hv = *(const ulonglong2*)&hp[s][4 * k4];
                acc[s] = ffma2(wlo, hv.x, acc[s]);
                acc[s] = ffma2(whi, hv.y, acc[s]);
            }
            wc = wn;
        }
#pragma unroll
        for (int s = 0; s < NB; s++) {
            float2 v = upk2(acc[s]);
            float z = v.x + v.y;
            act[s][j] = (gt == 2) ? tanh_f(z) : sigm(z);
        }
        __syncthreads();

#pragma unroll
        for (int r = 0; r < 3; r++) {
            int s = sb + 4 * r;
            float gi = act[s][m], gf = act[s][m + 128], gg = act[s][m + 256], go = act[s][m + 384];
            float c = fmaf(gf, csr[r], gi * gg);
            csr[r] = c;
            float h = go * tanh_f(c);
            hp[s][m] = h;
            g_out1[((size_t)(sbase + s) * T + t) * H + m] = h;
            sum[r] += h;
            sq[r] = fmaf(h, h, sq[r]);
        }
        __syncthreads();
    }
#pragma unroll
    for (int r = 0; r < 3; r++) {
        int idx = (sbase + sb + 4 * r) * H + m;
        g_ps1[idx] = sum[r];
        g_pq1[idx] = sq[r];
    }
}

// ---------- BN stats reduce (fp64 tree, deterministic) ----------
__global__ void __launch_bounds__(128)
bn_reduce_kernel(const float* __restrict__ ps, const float* __restrict__ pq,
                 const float* __restrict__ gamma, const float* __restrict__ beta,
                 float2* __restrict__ bnout) {
    __shared__ double rs[128], rq[128];
    int cidx = blockIdx.x;               // in*H + c
    int in = cidx >> 7, c = cidx & 127;
    int t = threadIdx.x;
    double s = 0.0, q = 0.0;
    for (int b = t; b < B; b += 128) {
        int idx = (in * B + b) * H + c;
        s += (double)ps[idx];
        q += (double)pq[idx];
    }
    rs[t] = s; rq[t] = q;
    __syncthreads();
    for (int off = 64; off > 0; off >>= 1) {
        if (t < off) { rs[t] += rs[t + off]; rq[t] += rq[t + off]; }
        __syncthreads();
    }
    if (t == 0) {
        double n = (double)B * T;
        double mean = rs[0] / n;
        double var = rq[0] / n - mean * mean;
        float scale = gamma[c] * (float)rsqrt(var + 1e-5);
        float shift = beta[c] - (float)mean * scale;
        bnout[cidx] = make_float2(scale, shift);
    }
}

// ---------- layer 2 LSTM (BN1 + Wih2*x folded, K=256) ----------
__global__ void __launch_bounds__(NTH, 1)
lstm2_kernel() {
    __shared__ __align__(16) float hp[NB][H];
    __shared__ __align__(16) float xq[NB][H];
    __shared__ float act[NB][G4];

    const int tid = threadIdx.x;
    const int j = tid;
    const int sbase = blockIdx.x * NB;

    const float bias = g_b2[j];

    const int m  = tid & 127;
    const int sb = tid >> 7;
    float sc[3], sh[3];
    float csr[3] = {0,0,0}, sum[3] = {0,0,0}, sq[3] = {0,0,0};
#pragma unroll
    for (int r = 0; r < 3; r++) {
        int in = (sbase + sb + 4 * r) >> 9;
        float2 bn = g_bn1[in * H + m];
        sc[r] = bn.x; sh[r] = bn.y;
    }
    {
        float* f = &hp[0][0];
#pragma unroll
        for (int r = 0; r < 3; r++) f[tid + NTH * r] = 0.f;
    }
    __syncthreads();

    const int gt = j >> 7;

    for (int t = 0; t < T; t++) {
#pragma unroll
        for (int r = 0; r < 3; r++) {
            int s = sb + 4 * r;
            float o = g_out1[((size_t)(sbase + s) * T + t) * H + m];
            xq[s][m] = fmaf(o, sc[r], sh[r]);
        }
        __syncthreads();

        ull acc[NB];
#pragma unroll
        for (int s = 0; s < NB; s++) acc[s] = pk2(bias, 0.f);

        // interleaved double-buffered streams: W2i (vs xq) and W2h (vs hp)
        float4 wic = __ldg(&g_W2i[j]);
        float4 whc = __ldg(&g_W2h[j]);
#pragma unroll 4
        for (int k4 = 0; k4 < 32; k4++) {
            int nk = ((k4 + 1) & 31) << 9;
            float4 win = __ldg(&g_W2i[nk + j]);
            float4 whn = __ldg(&g_W2h[nk + j]);
            ull wilo = pk2(wic.x, wic.y), wihi = pk2(wic.z, wic.w);
            ull whlo = pk2(whc.x, whc.y), whhi = pk2(whc.z, whc.w);
#pragma unroll
            for (int s = 0; s < NB; s++) {
                ulonglong2 xv = *(const ulonglong2*)&xq[s][4 * k4];
                ulonglong2 hv = *(const ulonglong2*)&hp[s][4 * k4];
                acc[s] = ffma2(wilo, xv.x, acc[s]);
                acc[s] = ffma2(wihi, xv.y, acc[s]);
                acc[s] = ffma2(whlo, hv.x, acc[s]);
                acc[s] = ffma2(whhi, hv.y, acc[s]);
            }
            wic = win; whc = whn;
        }
#pragma unroll
        for (int s = 0; s < NB; s++) {
            float2 v = upk2(acc[s]);
            float z = v.x + v.y;
            act[s][j] = (gt == 2) ? tanh_f(z) : sigm(z);
        }
        __syncthreads();

#pragma unroll
        for (int r = 0; r < 3; r++) {
            int s = sb + 4 * r;
            float gi = act[s][m], gf = act[s][m + 128], gg = act[s][m + 256], go = act[s][m + 384];
            float c = fmaf(gf, csr[r], gi * gg);
            csr[r] = c;
            float h = go * tanh_f(c);
            hp[s][m] = h;
            sum[r] += h;
            sq[r] = fmaf(h, h, sq[r]);
            if (t == T - 1) g_lasth[(sbase + s) * H + m] = h;
        }
        __syncthreads();
    }
#pragma unroll
    for (int r = 0; r < 3; r++) {
        int idx = (sbase + sb + 4 * r) * H + m;
        g_ps2[idx] = sum[r];
        g_pq2[idx] = sq[r];
    }
}

// ---------- FC + L2 normalize ----------
__global__ void __launch_bounds__(128)
final_kernel(const float* __restrict__ fcW, const float* __restrict__ fcb, float* __restrict__ out) {
    __shared__ float xn[H];
    __shared__ float emb[H];
    __shared__ float red[128];
    int s = blockIdx.x, j = threadIdx.x;
    int in = s >> 9, b = s & 511;

    float2 bn = g_bn2[in * H + j];
    xn[j] = fmaf(g_lasth[s * H + j], bn.x, bn.y);
    __syncthreads();

    float e = fcb[j];
    const float* wrow = fcW + j * H;
#pragma unroll 4
    for (int k = 0; k < H; k++) e = fmaf(__ldg(&wrow[k]), xn[k], e);
    emb[j] = e;
    red[j] = e * e;
    __syncthreads();
    for (int off = 64; off > 0; off >>= 1) {
        if (j < off) red[j] += red[j + off];
        __syncthreads();
    }
    float norm = sqrtf(red[0]);
    float inv = 1.f / fmaxf(norm, 1e-12f);
    out[((size_t)in * B + b) * H + j] = emb[j] * inv;
}

extern "C" void kernel_launch(void* const* d_in, const int* in_sizes, int n_in,
                              void* d_out, int out_size) {
    const float* a    = (const float*)d_in[0];
    const float* p    = (const float*)d_in[1];
    const float* n    = (const float*)d_in[2];
    const float* Wih1 = (const float*)d_in[3];
    const float* Whh1 = (const float*)d_in[4];
    const float* bih1 = (const float*)d_in[5];
    const float* bhh1 = (const float*)d_in[6];
    const float* g1   = (const float*)d_in[7];
    const float* b1   = (const float*)d_in[8];
    const float* Wih2 = (const float*)d_in[9];
    const float* Whh2 = (const float*)d_in[10];
    const float* bih2 = (const float*)d_in[11];
    const float* bhh2 = (const float*)d_in[12];
    const float* g2   = (const float*)d_in[13];
    const float* b2   = (const float*)d_in[14];
    const float* fcW  = (const float*)d_in[15];
    const float* fcb  = (const float*)d_in[16];
    float* out = (float*)d_out;

    float2 *bn1p, *bn2p;
    cudaGetSymbolAddress((void**)&bn1p, g_bn1);
    cudaGetSymbolAddress((void**)&bn2p, g_bn2);
    float *ps1, *pq1, *ps2, *pq2;
    cudaGetSymbolAddress((void**)&ps1, g_ps1);
    cudaGetSymbolAddress((void**)&pq1, g_pq1);
    cudaGetSymbolAddress((void**)&ps2, g_ps2);
    cudaGetSymbolAddress((void**)&pq2, g_pq2);

    prep_kernel<<<64, 256>>>(Wih1, Whh1, bih1, bhh1, Wih2, Whh2, bih2, bhh2);
    lstm1_kernel<<<NBLK, NTH>>>(a, p, n);
    bn_reduce_kernel<<<3 * H, 128>>>(ps1, pq1, g1, b1, bn1p);
    lstm2_kernel<<<NBLK, NTH>>>();
    bn_reduce_kernel<<<3 * H, 128>>>(ps2, pq2, g2, b2, bn2p);
    final_kernel<<<S, 128>>>(fcW, fcb, out);
}

// round 7
// speedup vs baseline: 1.2217x; 1.2217x over previous
#include <cuda_runtime.h>
#include <math.h>
#include <stdint.h>

constexpr int H    = 128;
constexpr int G4   = 512;
constexpr int B    = 512;
constexpr int T    = 128;
constexpr int S    = 1536;   // 3 inputs * B
constexpr int NB   = 12;     // seqs per block
constexpr int NBLK = 128;
constexpr int NTH  = 512;

// k4-major packed weights: g_W[k4*512 + j] = {W[j][4k4..4k4+3]}
__device__ float4 g_W1h[32 * 512];
__device__ float4 g_W2i[32 * 512];
__device__ float4 g_W2h[32 * 512];
__device__ float  g_b1[512];
__device__ float  g_b2[512];
__device__ float  g_wx1[5 * 512];          // [d][j]
__device__ float  g_out1[(size_t)S * T * H];
__device__ float  g_lasth[S * H];
__device__ float  g_ps1[S * H];
__device__ float  g_pq1[S * H];
__device__ float  g_ps2[S * H];
__device__ float  g_pq2[S * H];
__device__ float2 g_bn1[3 * H];
__device__ float2 g_bn2[3 * H];

typedef unsigned long long ull;

__device__ __forceinline__ ull pk2(float x, float y) {
    ull r;
    asm("mov.b64 %0, {%1,%2};" : "=l"(r) : "r"(__float_as_uint(x)), "r"(__float_as_uint(y)));
    return r;
}
__device__ __forceinline__ float2 upk2(ull v) {
    unsigned lo, hi;
    asm("mov.b64 {%0,%1}, %2;" : "=r"(lo), "=r"(hi) : "l"(v));
    return make_float2(__uint_as_float(lo), __uint_as_float(hi));
}
__device__ __forceinline__ ull ffma2(ull a, ull b, ull c) {
    ull d;
    asm("fma.rn.f32x2 %0, %1, %2, %3;" : "=l"(d) : "l"(a), "l"(b), "l"(c));
    return d;
}
__device__ __forceinline__ float sigm(float x) {
    return __fdividef(1.f, 1.f + __expf(-x));
}
__device__ __forceinline__ float tanh_f(float x) {
    float e = __expf(-2.f * fabsf(x));
    float t = __fdividef(1.f - e, 1.f + e);
    return copysignf(t, x);
}

// ---------- pack weights ----------
__global__ void prep_kernel(const float* Wih1, const float* Whh1, const float* bih1, const float* bhh1,
                            const float* Wih2, const float* Whh2, const float* bih2, const float* bhh2) {
    int tid = blockIdx.x * blockDim.x + threadIdx.x;
    int stride = gridDim.x * blockDim.x;
    for (int idx = tid; idx < 32 * 512; idx += stride) {
        int k4 = idx >> 9, j = idx & 511;
        g_W1h[idx] = *(const float4*)&Whh1[j * H + 4 * k4];
        g_W2i[idx] = *(const float4*)&Wih2[j * H + 4 * k4];
        g_W2h[idx] = *(const float4*)&Whh2[j * H + 4 * k4];
    }
    for (int j = tid; j < 512; j += stride) {
        g_b1[j] = bih1[j] + bhh1[j];
        g_b2[j] = bih2[j] + bhh2[j];
        for (int d = 0; d < 5; d++) g_wx1[d * 512 + j] = Wih1[j * 5 + d];
    }
}

// ---------- layer 1 LSTM : 128 blocks x 512 thr, 12 seqs/block ----------
// thread = gate-pair (jA = tid&255, jB = jA+256) x k-half (kh = tid>>8)
__global__ void __launch_bounds__(NTH, 1)
lstm1_kernel(const float* __restrict__ xa, const float* __restrict__ xp, const float* __restrict__ xn) {
    __shared__ __align__(16) float hp[NB][H];    // 6 KB
    __shared__ float act[NB][G4];                // 24 KB (partials then activations)
    __shared__ float xps[NB][5];

    const int tid = threadIdx.x;
    const int jA  = tid & 255;
    const int jB  = jA + 256;
    const int kh  = tid >> 8;        // 0 or 1
    const int kb  = kh << 4;         // k4 base: 0 or 16
    const int sbase = blockIdx.x * NB;

    const float biasA = g_b1[jA];
    const float biasB = g_b1[jB];
    float wxA[5], wxB[5];
#pragma unroll
    for (int d = 0; d < 5; d++) { wxA[d] = g_wx1[d * 512 + jA]; wxB[d] = g_wx1[d * 512 + jB]; }

    // phase-2 mapping: slot r -> u = tid + 512r, s = (tid>>7) + 4r, m = tid & 127
    const int m  = tid & 127;
    const int sb = tid >> 7;
    float csr[3] = {0,0,0}, sum[3] = {0,0,0}, sq[3] = {0,0,0};

    const float* xptr = xa; int xoff = 0, xsl = 0, xd = 0;
    const bool is_loader = (tid < NB * 5);
    if (is_loader) {
        xsl = tid / 5; xd = tid - 5 * xsl;
        int s = sbase + xsl, in = s >> 9, b = s & 511;
        xptr = (in == 0) ? xa : ((in == 1) ? xp : xn);
        xoff = b * (T * 5) + xd;
    }
    {
        float* f = &hp[0][0];
#pragma unroll
        for (int r = 0; r < 3; r++) f[tid + NTH * r] = 0.f;
    }
    if (is_loader) xps[xsl][xd] = __ldg(&xptr[xoff]);   // pre-stage t=0
    __syncthreads();

    for (int t = 0; t < T; t++) {
        // ---- half-matvec ----
        ull accA[NB], accB[NB];
        if (kh == 0) {
#pragma unroll
            for (int s = 0; s < NB; s++) {
                float dA = biasA, dB = biasB;
#pragma unroll
                for (int d = 0; d < 5; d++) {
                    float xv = xps[s][d];
                    dA = fmaf(wxA[d], xv, dA);
                    dB = fmaf(wxB[d], xv, dB);
                }
                accA[s] = pk2(dA, 0.f);
                accB[s] = pk2(dB, 0.f);
            }
        } else {
#pragma unroll
            for (int s = 0; s < NB; s++) { accA[s] = 0ull; accB[s] = 0ull; }
        }
#pragma unroll 4
        for (int kk = 0; kk < 16; kk++) {
            int k4 = kb + kk;
            float4 wA = __ldg(&g_W1h[(k4 << 9) + jA]);
            float4 wB = __ldg(&g_W1h[(k4 << 9) + jB]);
            ull wAlo = pk2(wA.x, wA.y), wAhi = pk2(wA.z, wA.w);
            ull wBlo = pk2(wB.x, wB.y), wBhi = pk2(wB.z, wB.w);
#pragma unroll
            for (int s = 0; s < NB; s++) {
                ulonglong2 hv = *(const ulonglong2*)&hp[s][4 * k4];
                accA[s] = ffma2(wAlo, hv.x, accA[s]);
                accA[s] = ffma2(wAhi, hv.y, accA[s]);
                accB[s] = ffma2(wBlo, hv.x, accB[s]);
                accB[s] = ffma2(wBhi, hv.y, accB[s]);
            }
        }
        // ---- partial reduce + activation ----
        if (kh == 0) {
#pragma unroll
            for (int s = 0; s < NB; s++) {
                float2 vA = upk2(accA[s]), vB = upk2(accB[s]);
                act[s][jA] = vA.x + vA.y;
                act[s][jB] = vB.x + vB.y;
            }
        }
        __syncthreads();
        if (kh == 1) {
            const bool btanh = (jA < 128);   // jB in [256,384) -> g gate
#pragma unroll
            for (int s = 0; s < NB; s++) {
                float2 vA = upk2(accA[s]), vB = upk2(accB[s]);
                float zA = act[s][jA] + vA.x + vA.y;
                float zB = act[s][jB] + vB.x + vB.y;
                act[s][jA] = sigm(zA);                       // i or f
                act[s][jB] = btanh ? tanh_f(zB) : sigm(zB);  // g or o
            }
        }
        __syncthreads();

        // ---- phase 2: c/h update + stage next x ----
        if (is_loader && t + 1 < T) xps[xsl][xd] = __ldg(&xptr[xoff + (t + 1) * 5]);
#pragma unroll
        for (int r = 0; r < 3; r++) {
            int s = sb + 4 * r;
            float gi = act[s][m], gf = act[s][m + 128], gg = act[s][m + 256], go = act[s][m + 384];
            float c = fmaf(gf, csr[r], gi * gg);
            csr[r] = c;
            float h = go * tanh_f(c);
            hp[s][m] = h;
            g_out1[((size_t)(sbase + s) * T + t) * H + m] = h;
            sum[r] += h;
            sq[r] = fmaf(h, h, sq[r]);
        }
        __syncthreads();
    }
#pragma unroll
    for (int r = 0; r < 3; r++) {
        int idx = (sbase + sb + 4 * r) * H + m;
        g_ps1[idx] = sum[r];
        g_pq1[idx] = sq[r];
    }
}

// ---------- BN stats reduce (fp64 tree, deterministic) ----------
__global__ void __launch_bounds__(128)
bn_reduce_kernel(const float* __restrict__ ps, const float* __restrict__ pq,
                 const float* __restrict__ gamma, const float* __restrict__ beta,
                 float2* __restrict__ bnout) {
    __shared__ double rs[128], rq[128];
    int cidx = blockIdx.x;               // in*H + c
    int in = cidx >> 7, c = cidx & 127;
    int t = threadIdx.x;
    double s = 0.0, q = 0.0;
    for (int b = t; b < B; b += 128) {
        int idx = (in * B + b) * H + c;
        s += (double)ps[idx];
        q += (double)pq[idx];
    }
    rs[t] = s; rq[t] = q;
    __syncthreads();
    for (int off = 64; off > 0; off >>= 1) {
        if (t < off) { rs[t] += rs[t + off]; rq[t] += rq[t + off]; }
        __syncthreads();
    }
    if (t == 0) {
        double n = (double)B * T;
        double mean = rs[0] / n;
        double var = rq[0] / n - mean * mean;
        float scale = gamma[c] * (float)rsqrt(var + 1e-5);
        float shift = beta[c] - (float)mean * scale;
        bnout[cidx] = make_float2(scale, shift);
    }
}

// ---------- layer 2 LSTM (BN1 + Wih2*x folded, K=256) ----------
__global__ void __launch_bounds__(NTH, 1)
lstm2_kernel() {
    __shared__ __align__(16) float hp[NB][H];
    __shared__ __align__(16) float xq[NB][H];
    __shared__ float act[NB][G4];

    const int tid = threadIdx.x;
    const int jA  = tid & 255;
    const int jB  = jA + 256;
    const int kh  = tid >> 8;
    const int kb  = kh << 4;
    const int sbase = blockIdx.x * NB;

    const float biasA = g_b2[jA];
    const float biasB = g_b2[jB];

    const int m  = tid & 127;
    const int sb = tid >> 7;
    float sc[3], sh[3];
    float csr[3] = {0,0,0}, sum[3] = {0,0,0}, sq[3] = {0,0,0};
#pragma unroll
    for (int r = 0; r < 3; r++) {
        int in = (sbase + sb + 4 * r) >> 9;
        float2 bn = g_bn1[in * H + m];
        sc[r] = bn.x; sh[r] = bn.y;
    }
    {
        float* f = &hp[0][0];
#pragma unroll
        for (int r = 0; r < 3; r++) f[tid + NTH * r] = 0.f;
    }
    // pre-stage t=0 x
#pragma unroll
    for (int r = 0; r < 3; r++) {
        int s = sb + 4 * r;
        float o = g_out1[((size_t)(sbase + s) * T + 0) * H + m];
        xq[s][m] = fmaf(o, sc[r], sh[r]);
    }
    __syncthreads();

    for (int t = 0; t < T; t++) {
        ull accA[NB], accB[NB];
        if (kh == 0) {
#pragma unroll
            for (int s = 0; s < NB; s++) { accA[s] = pk2(biasA, 0.f); accB[s] = pk2(biasB, 0.f); }
        } else {
#pragma unroll
            for (int s = 0; s < NB; s++) { accA[s] = 0ull; accB[s] = 0ull; }
        }
#pragma unroll 4
        for (int kk = 0; kk < 16; kk++) {
            int k4 = kb + kk;
            float4 wiA = __ldg(&g_W2i[(k4 << 9) + jA]);
            float4 wiB = __ldg(&g_W2i[(k4 << 9) + jB]);
            float4 whA = __ldg(&g_W2h[(k4 << 9) + jA]);
            float4 whB = __ldg(&g_W2h[(k4 << 9) + jB]);
            ull wiAlo = pk2(wiA.x, wiA.y), wiAhi = pk2(wiA.z, wiA.w);
            ull wiBlo = pk2(wiB.x, wiB.y), wiBhi = pk2(wiB.z, wiB.w);
            ull whAlo = pk2(whA.x, whA.y), whAhi = pk2(whA.z, whA.w);
            ull whBlo = pk2(whB.x, whB.y), whBhi = pk2(whB.z, whB.w);
#pragma unroll
            for (int s = 0; s < NB; s++) {
                ulonglong2 xv = *(const ulonglong2*)&xq[s][4 * k4];
                ulonglong2 hv = *(const ulonglong2*)&hp[s][4 * k4];
                accA[s] = ffma2(wiAlo, xv.x, accA[s]);
                accA[s] = ffma2(wiAhi, xv.y, accA[s]);
                accA[s] = ffma2(whAlo, hv.x, accA[s]);
                accA[s] = ffma2(whAhi, hv.y, accA[s]);
                accB[s] = ffma2(wiBlo, xv.x, accB[s]);
                accB[s] = ffma2(wiBhi, xv.y, accB[s]);
                accB[s] = ffma2(whBlo, hv.x, accB[s]);
                accB[s] = ffma2(whBhi, hv.y, accB[s]);
            }
        }
        if (kh == 0) {
#pragma unroll
            for (int s = 0; s < NB; s++) {
                float2 vA = upk2(accA[s]), vB = upk2(accB[s]);
                act[s][jA] = vA.x + vA.y;
                act[s][jB] = vB.x + vB.y;
            }
        }
        __syncthreads();
        if (kh == 1) {
            const bool btanh = (jA < 128);
#pragma unroll
            for (int s = 0; s < NB; s++) {
                float2 vA = upk2(accA[s]), vB = upk2(accB[s]);
                float zA = act[s][jA] + vA.x + vA.y;
                float zB = act[s][jB] + vB.x + vB.y;
                act[s][jA] = sigm(zA);
                act[s][jB] = btanh ? tanh_f(zB) : sigm(zB);
            }
        }
        __syncthreads();

#pragma unroll
        for (int r = 0; r < 3; r++) {
            int s = sb + 4 * r;
            float gi = act[s][m], gf = act[s][m + 128], gg = act[s][m + 256], go = act[s][m + 384];
            float c = fmaf(gf, csr[r], gi * gg);
            csr[r] = c;
            float h = go * tanh_f(c);
            hp[s][m] = h;
            sum[r] += h;
            sq[r] = fmaf(h, h, sq[r]);
            if (t == T - 1) {
                g_lasth[(sbase + s) * H + m] = h;
            } else {
                float o = g_out1[((size_t)(sbase + s) * T + (t + 1)) * H + m];
                xq[s][m] = fmaf(o, sc[r], sh[r]);
            }
        }
        __syncthreads();
    }
#pragma unroll
    for (int r = 0; r < 3; r++) {
        int idx = (sbase + sb + 4 * r) * H + m;
        g_ps2[idx] = sum[r];
        g_pq2[idx] = sq[r];
    }
}

// ---------- FC + L2 normalize ----------
__global__ void __launch_bounds__(128)
final_kernel(const float* __restrict__ fcW, const float* __restrict__ fcb, float* __restrict__ out) {
    __shared__ float xn[H];
    __shared__ float emb[H];
    __shared__ float red[128];
    int s = blockIdx.x, j = threadIdx.x;
    int in = s >> 9, b = s & 511;

    float2 bn = g_bn2[in * H + j];
    xn[j] = fmaf(g_lasth[s * H + j], bn.x, bn.y);
    __syncthreads();

    float e = fcb[j];
    const float* wrow = fcW + j * H;
#pragma unroll 4
    for (int k = 0; k < H; k++) e = fmaf(__ldg(&wrow[k]), xn[k], e);
    emb[j] = e;
    red[j] = e * e;
    __syncthreads();
    for (int off = 64; off > 0; off >>= 1) {
        if (j < off) red[j] += red[j + off];
        __syncthreads();
    }
    float norm = sqrtf(red[0]);
    float inv = 1.f / fmaxf(norm, 1e-12f);
    out[((size_t)in * B + b) * H + j] = emb[j] * inv;
}

extern "C" void kernel_launch(void* const* d_in, const int* in_sizes, int n_in,
                              void* d_out, int out_size) {
    const float* a    = (const float*)d_in[0];
    const float* p    = (const float*)d_in[1];
    const float* n    = (const float*)d_in[2];
    const float* Wih1 = (const float*)d_in[3];
    const float* Whh1 = (const float*)d_in[4];
    const float* bih1 = (const float*)d_in[5];
    const float* bhh1 = (const float*)d_in[6];
    const float* g1   = (const float*)d_in[7];
    const float* b1   = (const float*)d_in[8];
    const float* Wih2 = (const float*)d_in[9];
    const float* Whh2 = (const float*)d_in[10];
    const float* bih2 = (const float*)d_in[11];
    const float* bhh2 = (const float*)d_in[12];
    const float* g2   = (const float*)d_in[13];
    const float* b2   = (const float*)d_in[14];
    const float* fcW  = (const float*)d_in[15];
    const float* fcb  = (const float*)d_in[16];
    float* out = (float*)d_out;

    float2 *bn1p, *bn2p;
    cudaGetSymbolAddress((void**)&bn1p, g_bn1);
    cudaGetSymbolAddress((void**)&bn2p, g_bn2);
    float *ps1, *pq1, *ps2, *pq2;
    cudaGetSymbolAddress((void**)&ps1, g_ps1);
    cudaGetSymbolAddress((void**)&pq1, g_pq1);
    cudaGetSymbolAddress((void**)&ps2, g_ps2);
    cudaGetSymbolAddress((void**)&pq2, g_pq2);

    prep_kernel<<<64, 256>>>(Wih1, Whh1, bih1, bhh1, Wih2, Whh2, bih2, bhh2);
    lstm1_kernel<<<NBLK, NTH>>>(a, p, n);
    bn_reduce_kernel<<<3 * H, 128>>>(ps1, pq1, g1, b1, bn1p);
    lstm2_kernel<<<NBLK, NTH>>>();
    bn_reduce_kernel<<<3 * H, 128>>>(ps2, pq2, g2, b2, bn2p);
    final_kernel<<<S, 128>>>(fcW, fcb, out);
}

// round 8
// speedup vs baseline: 1.2854x; 1.0521x over previous
#include <cuda_runtime.h>
#include <math.h>
#include <stdint.h>

constexpr int H    = 128;
constexpr int B    = 512;
constexpr int T    = 128;
constexpr int S    = 1536;   // 3 inputs * B
constexpr int NB   = 12;     // seqs per block
constexpr int NBLK = 128;
constexpr int NTH  = 512;

constexpr int HPW  = 132;    // padded h/x row: cols 0..63 = m<64, cols 68..131 = m>=64
constexpr int HOFF = 68;
constexpr int ACTW = 528;    // act row: gates 0..255 at cols 0..255, gates 256..511 at cols 272..527

// k4-major packed weights: g_W[k4*512 + j] = {W[j][4k4..4k4+3]}
__device__ float4 g_W1h[32 * 512];
__device__ float4 g_W2i[32 * 512];
__device__ float4 g_W2h[32 * 512];
__device__ float  g_b1[512];
__device__ float  g_b2[512];
__device__ float  g_wx1[5 * 512];          // [d][j]
__device__ float  g_out1[(size_t)S * T * H];
__device__ float  g_lasth[S * H];
__device__ float  g_ps1[S * H];
__device__ float  g_pq1[S * H];
__device__ float  g_ps2[S * H];
__device__ float  g_pq2[S * H];
__device__ float2 g_bn1[3 * H];
__device__ float2 g_bn2[3 * H];

typedef unsigned long long ull;

__device__ __forceinline__ ull pk2(float x, float y) {
    ull r;
    asm("mov.b64 %0, {%1,%2};" : "=l"(r) : "r"(__float_as_uint(x)), "r"(__float_as_uint(y)));
    return r;
}
__device__ __forceinline__ float2 upk2(ull v) {
    unsigned lo, hi;
    asm("mov.b64 {%0,%1}, %2;" : "=r"(lo), "=r"(hi) : "l"(v));
    return make_float2(__uint_as_float(lo), __uint_as_float(hi));
}
__device__ __forceinline__ ull ffma2(ull a, ull b, ull c) {
    ull d;
    asm("fma.rn.f32x2 %0, %1, %2, %3;" : "=l"(d) : "l"(a), "l"(b), "l"(c));
    return d;
}
__device__ __forceinline__ float sigm(float x) {
    return __fdividef(1.f, 1.f + __expf(-x));
}

// ---------- pack weights ----------
__global__ void prep_kernel(const float* Wih1, const float* Whh1, const float* bih1, const float* bhh1,
                            const float* Wih2, const float* Whh2, const float* bih2, const float* bhh2) {
    int tid = blockIdx.x * blockDim.x + threadIdx.x;
    int stride = gridDim.x * blockDim.x;
    for (int idx = tid; idx < 32 * 512; idx += stride) {
        int k4 = idx >> 9, j = idx & 511;
        g_W1h[idx] = *(const float4*)&Whh1[j * H + 4 * k4];
        g_W2i[idx] = *(const float4*)&Wih2[j * H + 4 * k4];
        g_W2h[idx] = *(const float4*)&Whh2[j * H + 4 * k4];
    }
    for (int j = tid; j < 512; j += stride) {
        g_b1[j] = bih1[j] + bhh1[j];
        g_b2[j] = bih2[j] + bhh2[j];
        for (int d = 0; d < 5; d++) g_wx1[d * 512 + j] = Wih1[j * 5 + d];
    }
}

// ---------- layer 1 LSTM ----------
// thread = gate-pair p = tid>>1 (gates p, p+256) x k-half kh = tid&1 (lane parity)
__global__ void __launch_bounds__(NTH, 1)
lstm1_kernel(const float* __restrict__ xa, const float* __restrict__ xp, const float* __restrict__ xn) {
    __shared__ __align__(16) float hp[NB * HPW];
    __shared__ float act[NB * ACTW];
    __shared__ float xps[NB][5];

    const int tid = threadIdx.x;
    const int p   = tid >> 1;
    const int kh  = tid & 1;
    const int sbase = blockIdx.x * NB;

    // bias only on even lane (added once per gate)
    const float biasA = kh ? 0.f : g_b1[p];
    const float biasB = kh ? 0.f : g_b1[p + 256];
    // x-dot split: even lane d=0..2, odd lane d=3..4
    float wxA[3], wxB[3];
    const int nd = kh ? 2 : 3;
    const int d0 = kh ? 3 : 0;
#pragma unroll
    for (int d = 0; d < 3; d++) {
        int dd = d0 + d;
        wxA[d] = (d < nd) ? g_wx1[dd * 512 + p]       : 0.f;
        wxB[d] = (d < nd) ? g_wx1[dd * 512 + p + 256] : 0.f;
    }

    // activation constants (uniform MUFU path; tanh(z) = 2*sigm(2z)-1)
    const bool ktanh = kh && (p < 128);
    const float zmul = ktanh ? 2.f : 1.f;
    const float amul = ktanh ? 2.f : 1.f;
    const float aadd = ktanh ? -1.f : 0.f;
    const int  acol  = kh ? (p + 272) : p;

    // phase-2 mapping
    const int m  = tid & 127;
    const int cm = m + ((m >> 6) << 2);  // +4 pad for m>=64
    const int sb = tid >> 7;
    float csr[3] = {0,0,0}, sum[3] = {0,0,0}, sq[3] = {0,0,0};

    const float* xptr = xa; int xoff = 0, xsl = 0, xd = 0;
    const bool is_loader = (tid < NB * 5);
    if (is_loader) {
        xsl = tid / 5; xd = tid - 5 * xsl;
        int s = sbase + xsl, in = s >> 9, b = s & 511;
        xptr = (in == 0) ? xa : ((in == 1) ? xp : xn);
        xoff = b * (T * 5) + xd;
    }
    for (int i = tid; i < NB * HPW; i += NTH) hp[i] = 0.f;
    if (is_loader) xps[xsl][xd] = __ldg(&xptr[xoff]);
    __syncthreads();

    const float4* Wb = g_W1h + (kh ? (16 << 9) : 0);
    const int hbase0 = kh ? HOFF : 0;

    for (int t = 0; t < T; t++) {
        // prefetch next x (latency hidden behind matvec)
        float xnv = 0.f;
        if (is_loader && t + 1 < T) xnv = __ldg(&xptr[xoff + (t + 1) * 5]);

        ull accA[NB], accB[NB];
#pragma unroll
        for (int s = 0; s < NB; s++) {
            float dA = biasA, dB = biasB;
#pragma unroll
            for (int d = 0; d < 3; d++) {
                float xv = (d < nd) ? xps[s][d0 + d] : 0.f;
                dA = fmaf(wxA[d], xv, dA);
                dB = fmaf(wxB[d], xv, dB);
            }
            accA[s] = pk2(dA, 0.f);
            accB[s] = pk2(dB, 0.f);
        }

        float4 wAc = __ldg(Wb + p);
        float4 wBc = __ldg(Wb + p + 256);
#pragma unroll 4
        for (int kk = 0; kk < 16; kk++) {
            int nx = ((kk + 1) & 15) << 9;
            float4 wAn = __ldg(Wb + nx + p);
            float4 wBn = __ldg(Wb + nx + p + 256);
            ull wAlo = pk2(wAc.x, wAc.y), wAhi = pk2(wAc.z, wAc.w);
            ull wBlo = pk2(wBc.x, wBc.y), wBhi = pk2(wBc.z, wBc.w);
            const float* hrow = hp + hbase0 + 4 * kk;
#pragma unroll
            for (int s = 0; s < NB; s++) {
                ulonglong2 hv = *(const ulonglong2*)&hrow[s * HPW];
                accA[s] = ffma2(wAlo, hv.x, accA[s]);
                accA[s] = ffma2(wAhi, hv.y, accA[s]);
                accB[s] = ffma2(wBlo, hv.x, accB[s]);
                accB[s] = ffma2(wBhi, hv.y, accB[s]);
            }
            wAc = wAn; wBc = wBn;
        }

        // combine halves via shuffle, activate with uniform sigmoid path
#pragma unroll
        for (int s = 0; s < NB; s++) {
            float2 vA = upk2(accA[s]); float zA = vA.x + vA.y;
            float2 vB = upk2(accB[s]); float zB = vB.x + vB.y;
            zA += __shfl_xor_sync(0xffffffffu, zA, 1);
            zB += __shfl_xor_sync(0xffffffffu, zB, 1);
            float z = kh ? zB : zA;              // even lane -> gate p (i/f), odd -> p+256 (g/o)
            float sg = sigm(z * zmul);
            act[s * ACTW + acol] = fmaf(sg, amul, aadd);
        }
        __syncthreads();

        // phase 2
        if (is_loader && t + 1 < T) xps[xsl][xd] = xnv;
#pragma unroll
        for (int r = 0; r < 3; r++) {
            int s = sb + 4 * r;
            const float* arow = act + s * ACTW;
            float gi = arow[m], gf = arow[m + 128], gg = arow[m + 272], go = arow[m + 400];
            float c = fmaf(gf, csr[r], gi * gg);
            csr[r] = c;
            float th = fmaf(2.f, sigm(2.f * c), -1.f);
            float h = go * th;
            hp[s * HPW + cm] = h;
            g_out1[((size_t)(sbase + s) * T + t) * H + m] = h;
            sum[r] += h;
            sq[r] = fmaf(h, h, sq[r]);
        }
        __syncthreads();
    }
#pragma unroll
    for (int r = 0; r < 3; r++) {
        int idx = (sbase + sb + 4 * r) * H + m;
        g_ps1[idx] = sum[r];
        g_pq1[idx] = sq[r];
    }
}

// ---------- BN stats reduce (fp64 tree, deterministic) ----------
__global__ void __launch_bounds__(128)
bn_reduce_kernel(const float* __restrict__ ps, const float* __restrict__ pq,
                 const float* __restrict__ gamma, const float* __restrict__ beta,
                 float2* __restrict__ bnout) {
    __shared__ double rs[128], rq[128];
    int cidx = blockIdx.x;
    int in = cidx >> 7, c = cidx & 127;
    int t = threadIdx.x;
    double s = 0.0, q = 0.0;
    for (int b = t; b < B; b += 128) {
        int idx = (in * B + b) * H + c;
        s += (double)ps[idx];
        q += (double)pq[idx];
    }
    rs[t] = s; rq[t] = q;
    __syncthreads();
    for (int off = 64; off > 0; off >>= 1) {
        if (t < off) { rs[t] += rs[t + off]; rq[t] += rq[t + off]; }
        __syncthreads();
    }
    if (t == 0) {
        double n = (double)B * T;
        double mean = rs[0] / n;
        double var = rq[0] / n - mean * mean;
        float scale = gamma[c] * (float)rsqrt(var + 1e-5);
        float shift = beta[c] - (float)mean * scale;
        bnout[cidx] = make_float2(scale, shift);
    }
}

// ---------- layer 2 LSTM (BN1 + Wih2*x folded, K=256) ----------
__global__ void __launch_bounds__(NTH, 1)
lstm2_kernel() {
    __shared__ __align__(16) float hp[NB * HPW];
    __shared__ __align__(16) float xq[NB * HPW];
    __shared__ float act[NB * ACTW];

    const int tid = threadIdx.x;
    const int p   = tid >> 1;
    const int kh  = tid & 1;
    const int sbase = blockIdx.x * NB;

    const float biasA = kh ? 0.f : g_b2[p];
    const float biasB = kh ? 0.f : g_b2[p + 256];

    const bool ktanh = kh && (p < 128);
    const float zmul = ktanh ? 2.f : 1.f;
    const float amul = ktanh ? 2.f : 1.f;
    const float aadd = ktanh ? -1.f : 0.f;
    const int  acol  = kh ? (p + 272) : p;

    const int m  = tid & 127;
    const int cm = m + ((m >> 6) << 2);
    const int sb = tid >> 7;
    float sc[3], sh[3];
    float csr[3] = {0,0,0}, sum[3] = {0,0,0}, sq[3] = {0,0,0};
#pragma unroll
    for (int r = 0; r < 3; r++) {
        int in = (sbase + sb + 4 * r) >> 9;
        float2 bn = g_bn1[in * H + m];
        sc[r] = bn.x; sh[r] = bn.y;
    }
    for (int i = tid; i < NB * HPW; i += NTH) { hp[i] = 0.f; }
    // pre-stage t=0 x
#pragma unroll
    for (int r = 0; r < 3; r++) {
        int s = sb + 4 * r;
        float o = g_out1[((size_t)(sbase + s) * T + 0) * H + m];
        xq[s * HPW + cm] = fmaf(o, sc[r], sh[r]);
    }
    __syncthreads();

    const float4* Wib = g_W2i + (kh ? (16 << 9) : 0);
    const float4* Whb = g_W2h + (kh ? (16 << 9) : 0);
    const int hbase0 = kh ? HOFF : 0;

    for (int t = 0; t < T; t++) {
        // prefetch next-step x from global (hidden behind matvec)
        float ov[3];
        if (t + 1 < T) {
#pragma unroll
            for (int r = 0; r < 3; r++) {
                int s = sb + 4 * r;
                ov[r] = __ldg(&g_out1[((size_t)(sbase + s) * T + (t + 1)) * H + m]);
            }
        }

        ull accA[NB], accB[NB];
#pragma unroll
        for (int s = 0; s < NB; s++) { accA[s] = pk2(biasA, 0.f); accB[s] = pk2(biasB, 0.f); }

        float4 wiAc = __ldg(Wib + p);
        float4 wiBc = __ldg(Wib + p + 256);
        float4 whAc = __ldg(Whb + p);
        float4 whBc = __ldg(Whb + p + 256);
#pragma unroll 4
        for (int kk = 0; kk < 16; kk++) {
            int nx = ((kk + 1) & 15) << 9;
            float4 wiAn = __ldg(Wib + nx + p);
            float4 wiBn = __ldg(Wib + nx + p + 256);
            float4 whAn = __ldg(Whb + nx + p);
            float4 whBn = __ldg(Whb + nx + p + 256);
            ull wiAlo = pk2(wiAc.x, wiAc.y), wiAhi = pk2(wiAc.z, wiAc.w);
            ull wiBlo = pk2(wiBc.x, wiBc.y), wiBhi = pk2(wiBc.z, wiBc.w);
            ull whAlo = pk2(whAc.x, whAc.y), whAhi = pk2(whAc.z, whAc.w);
            ull whBlo = pk2(whBc.x, whBc.y), whBhi = pk2(whBc.z, whBc.w);
            const float* xrow = xq + hbase0 + 4 * kk;
            const float* hrow = hp + hbase0 + 4 * kk;
#pragma unroll
            for (int s = 0; s < NB; s++) {
                ulonglong2 xv = *(const ulonglong2*)&xrow[s * HPW];
                ulonglong2 hv = *(const ulonglong2*)&hrow[s * HPW];
                accA[s] = ffma2(wiAlo, xv.x, accA[s]);
                accA[s] = ffma2(wiAhi, xv.y, accA[s]);
                accA[s] = ffma2(whAlo, hv.x, accA[s]);
                accA[s] = ffma2(whAhi, hv.y, accA[s]);
                accB[s] = ffma2(wiBlo, xv.x, accB[s]);
                accB[s] = ffma2(wiBhi, xv.y, accB[s]);
                accB[s] = ffma2(whBlo, hv.x, accB[s]);
                accB[s] = ffma2(whBhi, hv.y, accB[s]);
            }
            wiAc = wiAn; wiBc = wiBn; whAc = whAn; whBc = whBn;
        }

#pragma unroll
        for (int s = 0; s < NB; s++) {
            float2 vA = upk2(accA[s]); float zA = vA.x + vA.y;
            float2 vB = upk2(accB[s]); float zB = vB.x + vB.y;
            zA += __shfl_xor_sync(0xffffffffu, zA, 1);
            zB += __shfl_xor_sync(0xffffffffu, zB, 1);
            float z = kh ? zB : zA;
            float sg = sigm(z * zmul);
            act[s * ACTW + acol] = fmaf(sg, amul, aadd);
        }
        __syncthreads();

#pragma unroll
        for (int r = 0; r < 3; r++) {
            int s = sb + 4 * r;
            const float* arow = act + s * ACTW;
            float gi = arow[m], gf = arow[m + 128], gg = arow[m + 272], go = arow[m + 400];
            float c = fmaf(gf, csr[r], gi * gg);
            csr[r] = c;
            float th = fmaf(2.f, sigm(2.f * c), -1.f);
            float h = go * th;
            hp[s * HPW + cm] = h;
            sum[r] += h;
            sq[r] = fmaf(h, h, sq[r]);
            if (t == T - 1) {
                g_lasth[(sbase + s) * H + m] = h;
            } else {
                xq[s * HPW + cm] = fmaf(ov[r], sc[r], sh[r]);
            }
        }
        __syncthreads();
    }
#pragma unroll
    for (int r = 0; r < 3; r++) {
        int idx = (sbase + sb + 4 * r) * H + m;
        g_ps2[idx] = sum[r];
        g_pq2[idx] = sq[r];
    }
}

// ---------- FC + L2 normalize ----------
__global__ void __launch_bounds__(128)
final_kernel(const float* __restrict__ fcW, const float* __restrict__ fcb, float* __restrict__ out) {
    __shared__ float xn[H];
    __shared__ float emb[H];
    __shared__ float red[128];
    int s = blockIdx.x, j = threadIdx.x;
    int in = s >> 9, b = s & 511;

    float2 bn = g_bn2[in * H + j];
    xn[j] = fmaf(g_lasth[s * H + j], bn.x, bn.y);
    __syncthreads();

    float e = fcb[j];
    const float* wrow = fcW + j * H;
#pragma unroll 4
    for (int k = 0; k < H; k++) e = fmaf(__ldg(&wrow[k]), xn[k], e);
    emb[j] = e;
    red[j] = e * e;
    __syncthreads();
    for (int off = 64; off > 0; off >>= 1) {
        if (j < off) red[j] += red[j + off];
        __syncthreads();
    }
    float norm = sqrtf(red[0]);
    float inv = 1.f / fmaxf(norm, 1e-12f);
    out[((size_t)in * B + b) * H + j] = emb[j] * inv;
}

extern "C" void kernel_launch(void* const* d_in, const int* in_sizes, int n_in,
                              void* d_out, int out_size) {
    const float* a    = (const float*)d_in[0];
    const float* p    = (const float*)d_in[1];
    const float* n    = (const float*)d_in[2];
    const float* Wih1 = (const float*)d_in[3];
    const float* Whh1 = (const float*)d_in[4];
    const float* bih1 = (const float*)d_in[5];
    const float* bhh1 = (const float*)d_in[6];
    const float* g1   = (const float*)d_in[7];
    const float* b1   = (const float*)d_in[8];
    const float* Wih2 = (const float*)d_in[9];
    const float* Whh2 = (const float*)d_in[10];
    const float* bih2 = (const float*)d_in[11];
    const float* bhh2 = (const float*)d_in[12];
    const float* g2   = (const float*)d_in[13];
    const float* b2   = (const float*)d_in[14];
    const float* fcW  = (const float*)d_in[15];
    const float* fcb  = (const float*)d_in[16];
    float* out = (float*)d_out;

    float2 *bn1p, *bn2p;
    cudaGetSymbolAddress((void**)&bn1p, g_bn1);
    cudaGetSymbolAddress((void**)&bn2p, g_bn2);
    float *ps1, *pq1, *ps2, *pq2;
    cudaGetSymbolAddress((void**)&ps1, g_ps1);
    cudaGetSymbolAddress((void**)&pq1, g_pq1);
    cudaGetSymbolAddress((void**)&ps2, g_ps2);
    cudaGetSymbolAddress((void**)&pq2, g_pq2);

    prep_kernel<<<64, 256>>>(Wih1, Whh1, bih1, bhh1, Wih2, Whh2, bih2, bhh2);
    lstm1_kernel<<<NBLK, NTH>>>(a, p, n);
    bn_reduce_kernel<<<3 * H, 128>>>(ps1, pq1, g1, b1, bn1p);
    lstm2_kernel<<<NBLK, NTH>>>();
    bn_reduce_kernel<<<3 * H, 128>>>(ps2, pq2, g2, b2, bn2p);
    final_kernel<<<S, 128>>>(fcW, fcb, out);
}

// round 9
// speedup vs baseline: 1.2868x; 1.0011x over previous
#include <cuda_runtime.h>
#include <math.h>
#include <stdint.h>

constexpr int H    = 128;
constexpr int B    = 512;
constexpr int T    = 128;
constexpr int S    = 1536;   // 3 inputs * B
constexpr int NB   = 12;     // seqs per block
constexpr int NBLK = 128;
constexpr int NTH  = 512;

constexpr int HPW  = 132;    // padded h row: cols 0..63 = m<64, cols 68..131 = m>=64
constexpr int HOFF = 68;
constexpr int ACTW = 528;    // act row: gates 0..255 at 0..255, gates 256..511 at 272..527

// k4-major packed weights: g_W[k4*512 + j] = {W[j][4k4..4k4+3]}
__device__ float4 g_W1h[32 * 512];
__device__ float4 g_W2i[32 * 512];
__device__ float4 g_W2h[32 * 512];
__device__ float  g_b1[512];
__device__ float  g_b2[512];
__device__ float  g_wx1[5 * 512];          // [d][j]
__device__ float  g_out1[(size_t)S * T * H];
__device__ float  g_xpre[(size_t)S * T * 512];   // Wih2 @ BN1(out1), per token x gate
__device__ float  g_lasth[S * H];
__device__ float  g_ps1[S * H];
__device__ float  g_pq1[S * H];
__device__ float  g_ps2[S * H];
__device__ float  g_pq2[S * H];
__device__ float2 g_bn1[3 * H];
__device__ float2 g_bn2[3 * H];

typedef unsigned long long ull;

__device__ __forceinline__ ull pk2(float x, float y) {
    ull r;
    asm("mov.b64 %0, {%1,%2};" : "=l"(r) : "r"(__float_as_uint(x)), "r"(__float_as_uint(y)));
    return r;
}
__device__ __forceinline__ float2 upk2(ull v) {
    unsigned lo, hi;
    asm("mov.b64 {%0,%1}, %2;" : "=r"(lo), "=r"(hi) : "l"(v));
    return make_float2(__uint_as_float(lo), __uint_as_float(hi));
}
__device__ __forceinline__ ull ffma2(ull a, ull b, ull c) {
    ull d;
    asm("fma.rn.f32x2 %0, %1, %2, %3;" : "=l"(d) : "l"(a), "l"(b), "l"(c));
    return d;
}
__device__ __forceinline__ float sigm(float x) {
    return __fdividef(1.f, 1.f + __expf(-x));
}

// ---------- pack weights ----------
__global__ void prep_kernel(const float* Wih1, const float* Whh1, const float* bih1, const float* bhh1,
                            const float* Wih2, const float* Whh2, const float* bih2, const float* bhh2) {
    int tid = blockIdx.x * blockDim.x + threadIdx.x;
    int stride = gridDim.x * blockDim.x;
    for (int idx = tid; idx < 32 * 512; idx += stride) {
        int k4 = idx >> 9, j = idx & 511;
        g_W1h[idx] = *(const float4*)&Whh1[j * H + 4 * k4];
        g_W2i[idx] = *(const float4*)&Wih2[j * H + 4 * k4];
        g_W2h[idx] = *(const float4*)&Whh2[j * H + 4 * k4];
    }
    for (int j = tid; j < 512; j += stride) {
        g_b1[j] = bih1[j] + bhh1[j];
        g_b2[j] = bih2[j] + bhh2[j];
        for (int d = 0; d < 5; d++) g_wx1[d * 512 + j] = Wih1[j * 5 + d];
    }
}

// ---------- layer 1 LSTM (R8 structure) ----------
__global__ void __launch_bounds__(NTH, 1)
lstm1_kernel(const float* __restrict__ xa, const float* __restrict__ xp, const float* __restrict__ xn) {
    __shared__ __align__(16) float hp[NB * HPW];
    __shared__ float act[NB * ACTW];
    __shared__ float xps[NB][5];

    const int tid = threadIdx.x;
    const int p   = tid >> 1;
    const int kh  = tid & 1;
    const int sbase = blockIdx.x * NB;

    const float biasA = kh ? 0.f : g_b1[p];
    const float biasB = kh ? 0.f : g_b1[p + 256];
    float wxA[3], wxB[3];
    const int nd = kh ? 2 : 3;
    const int d0 = kh ? 3 : 0;
#pragma unroll
    for (int d = 0; d < 3; d++) {
        int dd = d0 + d;
        wxA[d] = (d < nd) ? g_wx1[dd * 512 + p]       : 0.f;
        wxB[d] = (d < nd) ? g_wx1[dd * 512 + p + 256] : 0.f;
    }

    const bool ktanh = kh && (p < 128);
    const float zmul = ktanh ? 2.f : 1.f;
    const float amul = ktanh ? 2.f : 1.f;
    const float aadd = ktanh ? -1.f : 0.f;
    const int  acol  = kh ? (p + 272) : p;

    const int m  = tid & 127;
    const int cm = m + ((m >> 6) << 2);
    const int sb = tid >> 7;
    float csr[3] = {0,0,0}, sum[3] = {0,0,0}, sq[3] = {0,0,0};

    const float* xptr = xa; int xoff = 0, xsl = 0, xd = 0;
    const bool is_loader = (tid < NB * 5);
    if (is_loader) {
        xsl = tid / 5; xd = tid - 5 * xsl;
        int s = sbase + xsl, in = s >> 9, b = s & 511;
        xptr = (in == 0) ? xa : ((in == 1) ? xp : xn);
        xoff = b * (T * 5) + xd;
    }
    for (int i = tid; i < NB * HPW; i += NTH) hp[i] = 0.f;
    if (is_loader) xps[xsl][xd] = __ldg(&xptr[xoff]);
    __syncthreads();

    const float4* Wb = g_W1h + (kh ? (16 << 9) : 0);
    const int hbase0 = kh ? HOFF : 0;

    for (int t = 0; t < T; t++) {
        float xnv = 0.f;
        if (is_loader && t + 1 < T) xnv = __ldg(&xptr[xoff + (t + 1) * 5]);

        ull accA[NB], accB[NB];
#pragma unroll
        for (int s = 0; s < NB; s++) {
            float dA = biasA, dB = biasB;
#pragma unroll
            for (int d = 0; d < 3; d++) {
                float xv = (d < nd) ? xps[s][d0 + d] : 0.f;
                dA = fmaf(wxA[d], xv, dA);
                dB = fmaf(wxB[d], xv, dB);
            }
            accA[s] = pk2(dA, 0.f);
            accB[s] = pk2(dB, 0.f);
        }

        float4 wAc = __ldg(Wb + p);
        float4 wBc = __ldg(Wb + p + 256);
#pragma unroll 4
        for (int kk = 0; kk < 16; kk++) {
            int nx = ((kk + 1) & 15) << 9;
            float4 wAn = __ldg(Wb + nx + p);
            float4 wBn = __ldg(Wb + nx + p + 256);
            ull wAlo = pk2(wAc.x, wAc.y), wAhi = pk2(wAc.z, wAc.w);
            ull wBlo = pk2(wBc.x, wBc.y), wBhi = pk2(wBc.z, wBc.w);
            const float* hrow = hp + hbase0 + 4 * kk;
#pragma unroll
            for (int s = 0; s < NB; s++) {
                ulonglong2 hv = *(const ulonglong2*)&hrow[s * HPW];
                accA[s] = ffma2(wAlo, hv.x, accA[s]);
                accA[s] = ffma2(wAhi, hv.y, accA[s]);
                accB[s] = ffma2(wBlo, hv.x, accB[s]);
                accB[s] = ffma2(wBhi, hv.y, accB[s]);
            }
            wAc = wAn; wBc = wBn;
        }

#pragma unroll
        for (int s = 0; s < NB; s++) {
            float2 vA = upk2(accA[s]); float zA = vA.x + vA.y;
            float2 vB = upk2(accB[s]); float zB = vB.x + vB.y;
            zA += __shfl_xor_sync(0xffffffffu, zA, 1);
            zB += __shfl_xor_sync(0xffffffffu, zB, 1);
            float z = kh ? zB : zA;
            float sg = sigm(z * zmul);
            act[s * ACTW + acol] = fmaf(sg, amul, aadd);
        }
        __syncthreads();

        if (is_loader && t + 1 < T) xps[xsl][xd] = xnv;
#pragma unroll
        for (int r = 0; r < 3; r++) {
            int s = sb + 4 * r;
            const float* arow = act + s * ACTW;
            float gi = arow[m], gf = arow[m + 128], gg = arow[m + 272], go = arow[m + 400];
            float c = fmaf(gf, csr[r], gi * gg);
            csr[r] = c;
            float th = fmaf(2.f, sigm(2.f * c), -1.f);
            float h = go * th;
            hp[s * HPW + cm] = h;
            g_out1[((size_t)(sbase + s) * T + t) * H + m] = h;
            sum[r] += h;
            sq[r] = fmaf(h, h, sq[r]);
        }
        __syncthreads();
    }
#pragma unroll
    for (int r = 0; r < 3; r++) {
        int idx = (sbase + sb + 4 * r) * H + m;
        g_ps1[idx] = sum[r];
        g_pq1[idx] = sq[r];
    }
}

// ---------- BN stats reduce (fp64 tree, deterministic) ----------
__global__ void __launch_bounds__(128)
bn_reduce_kernel(const float* __restrict__ ps, const float* __restrict__ pq,
                 const float* __restrict__ gamma, const float* __restrict__ beta,
                 float2* __restrict__ bnout) {
    __shared__ double rs[128], rq[128];
    int cidx = blockIdx.x;
    int in = cidx >> 7, c = cidx & 127;
    int t = threadIdx.x;
    double s = 0.0, q = 0.0;
    for (int b = t; b < B; b += 128) {
        int idx = (in * B + b) * H + c;
        s += (double)ps[idx];
        q += (double)pq[idx];
    }
    rs[t] = s; rq[t] = q;
    __syncthreads();
    for (int off = 64; off > 0; off >>= 1) {
        if (t < off) { rs[t] += rs[t + off]; rq[t] += rq[t + off]; }
        __syncthreads();
    }
    if (t == 0) {
        double n = (double)B * T;
        double mean = rs[0] / n;
        double var = rq[0] / n - mean * mean;
        float scale = gamma[c] * (float)rsqrt(var + 1e-5);
        float shift = beta[c] - (float)mean * scale;
        bnout[cidx] = make_float2(scale, shift);
    }
}

// ---------- xpre GEMM: g_xpre[tok][j] = sum_k Wih2[j][k] * BN1(out1)[tok][k] ----------
// grid 12288 blocks x 256 threads; block = 16 tokens x 512 gates
__global__ void __launch_bounds__(256)
xpre_kernel() {
    __shared__ __align__(16) float xs[16][H];   // 8 KB
    const int tid = threadIdx.x;
    const int tok0 = blockIdx.x * 16;

    // load + BN1-normalize 16 token rows
#pragma unroll
    for (int it = 0; it < 2; it++) {
        int i = tid + it * 256;          // 0..511 float4s
        int tl = i >> 5, f4 = i & 31;
        int tok = tok0 + tl;
        float4 v = __ldg(((const float4*)g_out1) + (size_t)tok * 32 + f4);
        int in = (tok >> 7) >> 9;        // s = tok/T ; in = s/512
        int m0 = f4 * 4;
        float2 b0 = g_bn1[in * H + m0 + 0];
        float2 b1 = g_bn1[in * H + m0 + 1];
        float2 b2 = g_bn1[in * H + m0 + 2];
        float2 b3 = g_bn1[in * H + m0 + 3];
        xs[tl][m0 + 0] = fmaf(v.x, b0.x, b0.y);
        xs[tl][m0 + 1] = fmaf(v.y, b1.x, b1.y);
        xs[tl][m0 + 2] = fmaf(v.z, b2.x, b2.y);
        xs[tl][m0 + 3] = fmaf(v.w, b3.x, b3.y);
    }
    __syncthreads();

    const int p = tid;                   // gates p and p+256
    ull accA[16], accB[16];
#pragma unroll
    for (int tk = 0; tk < 16; tk++) { accA[tk] = 0ull; accB[tk] = 0ull; }

#pragma unroll 4
    for (int k4 = 0; k4 < 32; k4++) {
        float4 wA = __ldg(&g_W2i[(k4 << 9) + p]);
        float4 wB = __ldg(&g_W2i[(k4 << 9) + p + 256]);
        ull wAlo = pk2(wA.x, wA.y), wAhi = pk2(wA.z, wA.w);
        ull wBlo = pk2(wB.x, wB.y), wBhi = pk2(wB.z, wB.w);
#pragma unroll
        for (int tk = 0; tk < 16; tk++) {
            ulonglong2 xv = *(const ulonglong2*)&xs[tk][4 * k4];
            accA[tk] = ffma2(wAlo, xv.x, accA[tk]);
            accA[tk] = ffma2(wAhi, xv.y, accA[tk]);
            accB[tk] = ffma2(wBlo, xv.x, accB[tk]);
            accB[tk] = ffma2(wBhi, xv.y, accB[tk]);
        }
    }
#pragma unroll
    for (int tk = 0; tk < 16; tk++) {
        float2 vA = upk2(accA[tk]);
        float2 vB = upk2(accB[tk]);
        size_t base = (size_t)(tok0 + tk) * 512;
        g_xpre[base + p]       = vA.x + vA.y;
        g_xpre[base + p + 256] = vB.x + vB.y;
    }
}

// ---------- layer 2 LSTM: recurrent part only (Whh2), seed = bias + xpre ----------
__global__ void __launch_bounds__(NTH, 1)
lstm2_kernel() {
    __shared__ __align__(16) float hp[NB * HPW];
    __shared__ float act[NB * ACTW];

    const int tid = threadIdx.x;
    const int p   = tid >> 1;
    const int kh  = tid & 1;
    const int sbase = blockIdx.x * NB;

    // each lane owns ONE gate's seed: even -> gate p (A chain), odd -> gate p+256 (B chain)
    const int myGate = p + (kh ? 256 : 0);
    const float bias = g_b2[myGate];

    const bool ktanh = kh && (p < 128);
    const float zmul = ktanh ? 2.f : 1.f;
    const float amul = ktanh ? 2.f : 1.f;
    const float aadd = ktanh ? -1.f : 0.f;
    const int  acol  = kh ? (p + 272) : p;

    const int m  = tid & 127;
    const int cm = m + ((m >> 6) << 2);
    const int sb = tid >> 7;
    float csr[3] = {0,0,0}, sum[3] = {0,0,0}, sq[3] = {0,0,0};

    for (int i = tid; i < NB * HPW; i += NTH) hp[i] = 0.f;
    __syncthreads();

    const float4* Whb = g_W2h + (kh ? (16 << 9) : 0);
    const int hbase0 = kh ? HOFF : 0;

    for (int t = 0; t < T; t++) {
        // fetch this step's xpre seeds (consumed after the matvec -> latency hidden)
        float xv[NB];
#pragma unroll
        for (int s = 0; s < NB; s++)
            xv[s] = __ldg(&g_xpre[((size_t)(sbase + s) * T + t) * 512 + myGate]);

        ull accA[NB], accB[NB];
#pragma unroll
        for (int s = 0; s < NB; s++) { accA[s] = 0ull; accB[s] = 0ull; }

        float4 wAc = __ldg(Whb + p);
        float4 wBc = __ldg(Whb + p + 256);
#pragma unroll 4
        for (int kk = 0; kk < 16; kk++) {
            int nx = ((kk + 1) & 15) << 9;
            float4 wAn = __ldg(Whb + nx + p);
            float4 wBn = __ldg(Whb + nx + p + 256);
            ull wAlo = pk2(wAc.x, wAc.y), wAhi = pk2(wAc.z, wAc.w);
            ull wBlo = pk2(wBc.x, wBc.y), wBhi = pk2(wBc.z, wBc.w);
            const float* hrow = hp + hbase0 + 4 * kk;
#pragma unroll
            for (int s = 0; s < NB; s++) {
                ulonglong2 hv = *(const ulonglong2*)&hrow[s * HPW];
                accA[s] = ffma2(wAlo, hv.x, accA[s]);
                accA[s] = ffma2(wAhi, hv.y, accA[s]);
                accB[s] = ffma2(wBlo, hv.x, accB[s]);
                accB[s] = ffma2(wBhi, hv.y, accB[s]);
            }
            wAc = wAn; wBc = wBn;
        }

#pragma unroll
        for (int s = 0; s < NB; s++) {
            float2 vA = upk2(accA[s]); float zA = vA.x + vA.y;
            float2 vB = upk2(accB[s]); float zB = vB.x + vB.y;
            float seed = bias + xv[s];
            if (kh) zB += seed; else zA += seed;     // each gate's seed added exactly once
            zA += __shfl_xor_sync(0xffffffffu, zA, 1);
            zB += __shfl_xor_sync(0xffffffffu, zB, 1);
            float z = kh ? zB : zA;
            float sg = sigm(z * zmul);
            act[s * ACTW + acol] = fmaf(sg, amul, aadd);
        }
        __syncthreads();

#pragma unroll
        for (int r = 0; r < 3; r++) {
            int s = sb + 4 * r;
            const float* arow = act + s * ACTW;
            float gi = arow[m], gf = arow[m + 128], gg = arow[m + 272], go = arow[m + 400];
            float c = fmaf(gf, csr[r], gi * gg);
            csr[r] = c;
            float th = fmaf(2.f, sigm(2.f * c), -1.f);
            float h = go * th;
            hp[s * HPW + cm] = h;
            sum[r] += h;
            sq[r] = fmaf(h, h, sq[r]);
            if (t == T - 1) g_lasth[(sbase + s) * H + m] = h;
        }
        __syncthreads();
    }
#pragma unroll
    for (int r = 0; r < 3; r++) {
        int idx = (sbase + sb + 4 * r) * H + m;
        g_ps2[idx] = sum[r];
        g_pq2[idx] = sq[r];
    }
}

// ---------- FC + L2 normalize ----------
__global__ void __launch_bounds__(128)
final_kernel(const float* __restrict__ fcW, const float* __restrict__ fcb, float* __restrict__ out) {
    __shared__ float xn[H];
    __shared__ float emb[H];
    __shared__ float red[128];
    int s = blockIdx.x, j = threadIdx.x;
    int in = s >> 9, b = s & 511;

    float2 bn = g_bn2[in * H + j];
    xn[j] = fmaf(g_lasth[s * H + j], bn.x, bn.y);
    __syncthreads();

    float e = fcb[j];
    const float* wrow = fcW + j * H;
#pragma unroll 4
    for (int k = 0; k < H; k++) e = fmaf(__ldg(&wrow[k]), xn[k], e);
    emb[j] = e;
    red[j] = e * e;
    __syncthreads();
    for (int off = 64; off > 0; off >>= 1) {
        if (j < off) red[j] += red[j + off];
        __syncthreads();
    }
    float norm = sqrtf(red[0]);
    float inv = 1.f / fmaxf(norm, 1e-12f);
    out[((size_t)in * B + b) * H + j] = emb[j] * inv;
}

extern "C" void kernel_launch(void* const* d_in, const int* in_sizes, int n_in,
                              void* d_out, int out_size) {
    const float* a    = (const float*)d_in[0];
    const float* p    = (const float*)d_in[1];
    const float* n    = (const float*)d_in[2];
    const float* Wih1 = (const float*)d_in[3];
    const float* Whh1 = (const float*)d_in[4];
    const float* bih1 = (const float*)d_in[5];
    const float* bhh1 = (const float*)d_in[6];
    const float* g1   = (const float*)d_in[7];
    const float* b1   = (const float*)d_in[8];
    const float* Wih2 = (const float*)d_in[9];
    const float* Whh2 = (const float*)d_in[10];
    const float* bih2 = (const float*)d_in[11];
    const float* bhh2 = (const float*)d_in[12];
    const float* g2   = (const float*)d_in[13];
    const float* b2   = (const float*)d_in[14];
    const float* fcW  = (const float*)d_in[15];
    const float* fcb  = (const float*)d_in[16];
    float* out = (float*)d_out;

    float2 *bn1p, *bn2p;
    cudaGetSymbolAddress((void**)&bn1p, g_bn1);
    cudaGetSymbolAddress((void**)&bn2p, g_bn2);
    float *ps1, *pq1, *ps2, *pq2;
    cudaGetSymbolAddress((void**)&ps1, g_ps1);
    cudaGetSymbolAddress((void**)&pq1, g_pq1);
    cudaGetSymbolAddress((void**)&ps2, g_ps2);
    cudaGetSymbolAddress((void**)&pq2, g_pq2);

    prep_kernel<<<64, 256>>>(Wih1, Whh1, bih1, bhh1, Wih2, Whh2, bih2, bhh2);
    lstm1_kernel<<<NBLK, NTH>>>(a, p, n);
    bn_reduce_kernel<<<3 * H, 128>>>(ps1, pq1, g1, b1, bn1p);
    xpre_kernel<<<(S * T) / 16, 256>>>();
    lstm2_kernel<<<NBLK, NTH>>>();
    bn_reduce_kernel<<<3 * H, 128>>>(ps2, pq2, g2, b2, bn2p);
    final_kernel<<<S, 128>>>(fcW, fcb, out);
}